// round 6
// baseline (speedup 1.0000x reference)
#include <cuda_runtime.h>
#include <cuda_bf16.h>
#include <math.h>

#define BB 2
#define SS 2048
#define EE 768
#define HH 12
#define DHH 64
#define WW 256
#define GG 16
#define FFD 3072
#define NEGV (-1e9f)

#define NQKV (BB*HH*SS*DHH)   /* 3145728 */
#define NXE  (BB*SS*EE)       /* 3145728 */
#define NFF  (BB*SS*FFD)      /* 12582912 */

// ---------------- device scratch (no allocations allowed) ----------------
__device__ float g_q[NQKV];
__device__ float g_k[NQKV];
__device__ float g_v[NQKV];
__device__ float g_gq[NQKV];
__device__ float g_gk[NQKV];
__device__ float g_gv[NQKV];
__device__ float g_attn[NXE];   // attn output; later reused for FFN-down output
__device__ float g_h0[NXE];
__device__ float g_t1[NFF];
__device__ float g_t2[NFF];
__device__ float g_tbuf[BB*SS];

// ---------------- cumsum of global flags -> t ----------------
__global__ void mask_cumsum_kernel(const int* __restrict__ am,
                                   const int* __restrict__ gm,
                                   float* __restrict__ tb) {
    int b = blockIdx.x;
    __shared__ int mg[SS];
    for (int i = threadIdx.x; i < SS; i += blockDim.x)
        mg[i] = am[b*SS + i] * (gm[b*SS + i] + 1);
    __syncthreads();
    if (threadIdx.x == 0) {
        int c = 0;
        for (int i = 0; i < SS; i++) {
            c += (mg[i] == 2);
            tb[b*SS + i] = (mg[i] == 0) ? 0.f : (float)c;
        }
    }
}

// ---------------- generic SGEMM: C = (A[4096,K] @ W[K,N] + bias) * scale ----------------
// epi==0: plain row-major store. epi==1: scatter to (B,H,S,DH) head layout.
struct GemmArgs {
    const float* A;
    const float* Wm[6];
    const float* bias[6];
    float* out[6];
    float scale[6];
    int N, K, epi;
};

__global__ __launch_bounds__(256, 2) void sgemm_kernel(GemmArgs g) {
    const int z = blockIdx.z;
    const float* __restrict__ A = g.A;
    const float* __restrict__ W = g.Wm[z];
    const float* __restrict__ bias = g.bias[z];
    float* __restrict__ out = g.out[z];
    const int N = g.N, K = g.K;
    const int bm = blockIdx.x << 7, bn = blockIdx.y << 7;

    __shared__ float As[8][128];
    __shared__ float Bs[8][128];

    const int tid = threadIdx.x;
    const int tx = tid & 15, ty = tid >> 4;
    const int arow = tid >> 1, aseg = (tid & 1) << 2;
    const int brow = tid >> 5, bcol = (tid & 31) << 2;

    const float* Ap = A + (size_t)(bm + arow) * K + aseg;
    const float* Wp = W + (size_t)brow * N + bn + bcol;

    float acc[8][8];
#pragma unroll
    for (int i = 0; i < 8; i++)
#pragma unroll
        for (int j = 0; j < 8; j++) acc[i][j] = 0.f;

    for (int k0 = 0; k0 < K; k0 += 8) {
        float4 a4 = *(const float4*)(Ap + k0);
        float4 b4 = *(const float4*)(Wp + (size_t)k0 * N);
        As[aseg+0][arow] = a4.x; As[aseg+1][arow] = a4.y;
        As[aseg+2][arow] = a4.z; As[aseg+3][arow] = a4.w;
        *(float4*)&Bs[brow][bcol] = b4;
        __syncthreads();
#pragma unroll
        for (int kk = 0; kk < 8; kk++) {
            float af[8], bf[8];
#pragma unroll
            for (int i = 0; i < 8; i++) af[i] = As[kk][(ty<<3)+i];
#pragma unroll
            for (int j = 0; j < 8; j++) bf[j] = Bs[kk][(tx<<3)+j];
#pragma unroll
            for (int i = 0; i < 8; i++)
#pragma unroll
                for (int j = 0; j < 8; j++)
                    acc[i][j] = fmaf(af[i], bf[j], acc[i][j]);
        }
        __syncthreads();
    }

    const float sc = g.scale[z];
#pragma unroll
    for (int i = 0; i < 8; i++) {
        int row = bm + (ty<<3) + i;
#pragma unroll
        for (int j = 0; j < 8; j++) {
            int col = bn + (tx<<3) + j;
            float v = acc[i][j];
            if (bias) v += bias[col];
            v *= sc;
            if (g.epi == 0) {
                out[(size_t)row * N + col] = v;
            } else {
                int b = row >> 11, s = row & (SS-1);
                int h = col >> 6,  d = col & 63;
                out[(((size_t)(b*HH + h) * SS + s) << 6) + d] = v;
            }
        }
    }
}

// ---------------- RoPE on q and k (in-place) ----------------
__global__ void rope_kernel(float* __restrict__ q, float* __restrict__ k,
                            const float* __restrict__ tb) {
    int idx = blockIdx.x * blockDim.x + threadIdx.x;
    const int total = BB*HH*SS*32;
    if (idx >= total) return;
    int d   = idx & 31;
    int rem = idx >> 5;
    int s   = rem & (SS-1);
    int rem2 = rem >> 11;
    int h   = rem2 % HH;
    int b   = rem2 / HH;
    float tt = tb[b*SS + s];
    float inv_freq = expf(-(float)d * 0.28782313662425574f); // ln(10000)/32
    float sn, cs;
    sincosf(tt * inv_freq, &sn, &cs);
    size_t off = (((size_t)(b*HH + h) * SS + s) << 6) + d;
    float x1 = q[off], x2 = q[off + 32];
    q[off]      = x1*cs - x2*sn;
    q[off + 32] = x2*cs + x1*sn;
    x1 = k[off]; x2 = k[off + 32];
    k[off]      = x1*cs - x2*sn;
    k[off + 32] = x2*cs + x1*sn;
}

// ---------------- banded + global-key attention ----------------
// one block = 16 queries of one (b,h). 529 scores/query (16 global + 513 band).
__global__ __launch_bounds__(256) void band_attn_kernel(
    const float* __restrict__ q, const float* __restrict__ k, const float* __restrict__ v,
    const int* __restrict__ am, const int* __restrict__ gm,
    float* __restrict__ attn)
{
    const int b = blockIdx.z, h = blockIdx.y, base = blockIdx.x << 4;
    const int tid = threadIdx.x;
    const int p = tid >> 4, r = tid & 15;

    __shared__ float qs[16][64];          // 4 KB
    __shared__ float sc[16][536];         // 33.5 KB (529 used)
    __shared__ float ks[32][68];          // 8.5 KB (keys, reused for values)
    __shared__ unsigned char rmv[32];

    const float* qb = q + ((size_t)(b*HH + h) * SS) * DHH;
    const float* kb = k + ((size_t)(b*HH + h) * SS) * DHH;
    const float* vb = v + ((size_t)(b*HH + h) * SS) * DHH;

    // load q tile (16x64) and the 16 global keys
    {
        const float4* src = (const float4*)(qb + (size_t)base * DHH);
        float4* dst = (float4*)&qs[0][0];
        dst[tid] = src[tid];                       // exactly 256 float4
        const float4* ksrc = (const float4*)kb;    // rows 0..15
        int kk = tid >> 4, d4 = tid & 15;
        *((float4*)&ks[kk][d4*4]) = ksrc[tid];
    }
    __syncthreads();

    // global-key scores (idx 0..15), unmasked per reference
    {
        float s = 0.f;
        const float4* qp = (const float4*)qs[p];
        const float4* kp = (const float4*)&ks[r][0];
#pragma unroll
        for (int d4 = 0; d4 < 16; d4++) {
            float4 a = qp[d4], bb = kp[d4];
            s += a.x*bb.x + a.y*bb.y + a.z*bb.z + a.w*bb.w;
        }
        sc[p][r] = s;
    }
    __syncthreads();

    const int jmin = base - WW;
    // band scores: l in [0,512] <-> key j = base+p-W+l ; jrel = p+l in [0,527]
    for (int c = 0; c < 17; c++) {
        int j0 = jmin + c*32;
        for (int i = tid; i < 32*16; i += 256) {
            int kk = i >> 4, d4 = i & 15;
            int j = j0 + kk;
            float4 val = make_float4(0.f, 0.f, 0.f, 0.f);
            if (j >= 0 && j < SS) val = *(const float4*)(kb + (size_t)j*DHH + d4*4);
            *((float4*)&ks[kk][d4*4]) = val;
        }
        if (tid < 32) {
            int j = j0 + tid;
            int rm = 1;
            if (j >= 0 && j < SS) { int m = am[b*SS+j] * (gm[b*SS+j] + 1); rm = (m != 1); }
            rmv[tid] = (unsigned char)rm;
        }
        __syncthreads();
        int lbase = c*32 - p;
        int lo = lbase > 0 ? lbase : 0;
        int hi = lbase + 31; if (hi > 512) hi = 512;
        if (lo <= hi) {
            int m0 = (lo - r + 15) >> 4; if (m0 < 0) m0 = 0;
            int m1 = (hi - r) >= 0 ? ((hi - r) >> 4) : -1;
            const float4* qp = (const float4*)qs[p];
            for (int m = m0; m <= m1; m++) {
                int l = r + (m << 4);
                int kk = p + l - c*32;
                float s;
                if (rmv[kk]) s = NEGV;
                else {
                    s = 0.f;
                    const float4* kp = (const float4*)&ks[kk][0];
#pragma unroll
                    for (int d4 = 0; d4 < 16; d4++) {
                        float4 a = qp[d4], bb = kp[d4];
                        s += a.x*bb.x + a.y*bb.y + a.z*bb.z + a.w*bb.w;
                    }
                }
                sc[p][16 + l] = s;
            }
        }
        __syncthreads();
    }

    // softmax over 529 entries; 16 lanes per query
    float mx = -3.4e38f;
    for (int idx = r; idx < 529; idx += 16) mx = fmaxf(mx, sc[p][idx]);
#pragma unroll
    for (int o = 8; o; o >>= 1) mx = fmaxf(mx, __shfl_xor_sync(0xffffffffu, mx, o, 16));
    float sum = 0.f;
    for (int idx = r; idx < 529; idx += 16) {
        float e = __expf(sc[p][idx] - mx);
        sc[p][idx] = e;
        sum += e;
    }
#pragma unroll
    for (int o = 8; o; o >>= 1) sum += __shfl_xor_sync(0xffffffffu, sum, o, 16);
    float inv = 1.f / sum;
    __syncthreads();

    // AV: each lane owns d = 4r..4r+3
    float4 acc = make_float4(0.f, 0.f, 0.f, 0.f);
    {   // global values
        const float4* vsrc = (const float4*)vb;
        int kk = tid >> 4, d4 = tid & 15;
        *((float4*)&ks[kk][d4*4]) = vsrc[tid];
    }
    __syncthreads();
#pragma unroll
    for (int gidx = 0; gidx < 16; gidx++) {
        float pr = sc[p][gidx];
        float4 vv = *(const float4*)&ks[gidx][r*4];
        acc.x += pr*vv.x; acc.y += pr*vv.y; acc.z += pr*vv.z; acc.w += pr*vv.w;
    }
    __syncthreads();
    for (int c = 0; c < 17; c++) {
        int j0 = jmin + c*32;
        for (int i = tid; i < 32*16; i += 256) {
            int kk = i >> 4, d4 = i & 15;
            int j = j0 + kk;
            float4 val = make_float4(0.f, 0.f, 0.f, 0.f);
            if (j >= 0 && j < SS) val = *(const float4*)(vb + (size_t)j*DHH + d4*4);
            *((float4*)&ks[kk][d4*4]) = val;
        }
        __syncthreads();
        int lbase = c*32 - p;
        int lo = lbase > 0 ? lbase : 0;
        int hi = lbase + 31; if (hi > 512) hi = 512;
        for (int l = lo; l <= hi; l++) {
            int kk = p + l - c*32;
            float pr = sc[p][16 + l];
            float4 vv = *(const float4*)&ks[kk][r*4];
            acc.x += pr*vv.x; acc.y += pr*vv.y; acc.z += pr*vv.z; acc.w += pr*vv.w;
        }
        __syncthreads();
    }

    int iq = base + p;
    int mm = am[b*SS + iq] * (gm[b*SS + iq] + 1);
    float scl = (mm == 0) ? 0.f : inv;
    float4 o4 = make_float4(acc.x*scl, acc.y*scl, acc.z*scl, acc.w*scl);
    *(float4*)(attn + ((size_t)b*SS + iq)*EE + h*DHH + r*4) = o4;
}

// ---------------- global attention (overwrites attn rows < G) ----------------
__global__ __launch_bounds__(256) void global_attn_kernel(
    const float* __restrict__ gq, const float* __restrict__ gk, const float* __restrict__ gv,
    const int* __restrict__ am, const int* __restrict__ gm,
    float* __restrict__ attn)
{
    int g = blockIdx.x, h = blockIdx.y, b = blockIdx.z;
    int tid = threadIdx.x;
    __shared__ float sc[SS];
    __shared__ float qrow[64];
    __shared__ float red[8];
    __shared__ float redv[4][64];

    const float* gkb = gk + ((size_t)(b*HH + h) * SS) * DHH;
    const float* gvb = gv + ((size_t)(b*HH + h) * SS) * DHH;
    if (tid < 64) qrow[tid] = gq[(((size_t)(b*HH + h) * SS + g) << 6) + tid];
    __syncthreads();

    float lmax = -3.4e38f;
    for (int j = tid; j < SS; j += 256) {
        int m = am[b*SS + j] * (gm[b*SS + j] + 1);
        float s;
        if (m == 0) s = NEGV;
        else {
            s = 0.f;
            const float4* kp = (const float4*)(gkb + (size_t)j * DHH);
            const float4* qp = (const float4*)qrow;
#pragma unroll
            for (int d4 = 0; d4 < 16; d4++) {
                float4 a = qp[d4], bb = kp[d4];
                s += a.x*bb.x + a.y*bb.y + a.z*bb.z + a.w*bb.w;
            }
        }
        sc[j] = s;
        lmax = fmaxf(lmax, s);
    }
#pragma unroll
    for (int o = 16; o; o >>= 1) lmax = fmaxf(lmax, __shfl_xor_sync(0xffffffffu, lmax, o));
    if ((tid & 31) == 0) red[tid >> 5] = lmax;
    __syncthreads();
    float bmax = red[0];
#pragma unroll
    for (int w = 1; w < 8; w++) bmax = fmaxf(bmax, red[w]);

    float lsum = 0.f;
    for (int j = tid; j < SS; j += 256) {
        float e = __expf(sc[j] - bmax);
        sc[j] = e;
        lsum += e;
    }
#pragma unroll
    for (int o = 16; o; o >>= 1) lsum += __shfl_xor_sync(0xffffffffu, lsum, o);
    __syncthreads();
    if ((tid & 31) == 0) red[tid >> 5] = lsum;
    __syncthreads();
    float ssum = 0.f;
#pragma unroll
    for (int w = 0; w < 8; w++) ssum += red[w];
    float inv = 1.f / ssum;

    int grp = tid >> 6, d = tid & 63;
    float acc = 0.f;
    for (int j = grp; j < SS; j += 4) acc += sc[j] * gvb[(size_t)j * DHH + d];
    redv[grp][d] = acc;
    __syncthreads();
    if (grp == 0) {
        float o = (redv[0][d] + redv[1][d] + redv[2][d] + redv[3][d]) * inv;
        attn[((size_t)b*SS + g)*EE + h*DHH + d] = o;
    }
}

// ---------------- fused add + LayerNorm ----------------
__global__ __launch_bounds__(256) void add_ln_kernel(
    const float* __restrict__ a, const float* __restrict__ c,
    const float* __restrict__ gamma, const float* __restrict__ beta,
    float* __restrict__ out)
{
    int row = blockIdx.x;
    int tid = threadIdx.x;
    __shared__ float buf[EE];
    __shared__ float red[8];

    float local = 0.f;
#pragma unroll
    for (int i = 0; i < 3; i++) {
        int idx = tid + i*256;
        float v = a[(size_t)row*EE + idx] + c[(size_t)row*EE + idx];
        buf[idx] = v;
        local += v;
    }
#pragma unroll
    for (int o = 16; o; o >>= 1) local += __shfl_xor_sync(0xffffffffu, local, o);
    if ((tid & 31) == 0) red[tid >> 5] = local;
    __syncthreads();
    float s = 0.f;
#pragma unroll
    for (int w = 0; w < 8; w++) s += red[w];
    float mean = s * (1.f/768.f);

    float lv = 0.f;
#pragma unroll
    for (int i = 0; i < 3; i++) {
        float dd = buf[tid + i*256] - mean;
        lv += dd*dd;
    }
#pragma unroll
    for (int o = 16; o; o >>= 1) lv += __shfl_xor_sync(0xffffffffu, lv, o);
    __syncthreads();
    if ((tid & 31) == 0) red[tid >> 5] = lv;
    __syncthreads();
    float vs = 0.f;
#pragma unroll
    for (int w = 0; w < 8; w++) vs += red[w];
    float invstd = rsqrtf(vs * (1.f/768.f) + 1e-5f);

#pragma unroll
    for (int i = 0; i < 3; i++) {
        int idx = tid + i*256;
        out[(size_t)row*EE + idx] = (buf[idx] - mean) * invstd * gamma[idx] + beta[idx];
    }
}

// ---------------- SiLU(t1) * t2 -> t1 ----------------
__global__ void silu_mul_kernel(float* __restrict__ t1, const float* __restrict__ t2, int n) {
    int i = blockIdx.x * blockDim.x + threadIdx.x;
    if (i < n) {
        float a = t1[i];
        t1[i] = a / (1.f + expf(-a)) * t2[i];
    }
}

// ---------------- launch ----------------
extern "C" void kernel_launch(void* const* d_in, const int* in_sizes, int n_in,
                              void* d_out, int out_size) {
    (void)in_sizes; (void)n_in; (void)out_size;
    const float* x    = (const float*)d_in[0];
    const int*   am   = (const int*)d_in[1];
    const int*   gm   = (const int*)d_in[2];
    const float* Wq   = (const float*)d_in[3];  const float* bq  = (const float*)d_in[4];
    const float* Wk   = (const float*)d_in[5];  const float* bk  = (const float*)d_in[6];
    const float* Wv   = (const float*)d_in[7];  const float* bv  = (const float*)d_in[8];
    const float* Wqg  = (const float*)d_in[9];  const float* bqg = (const float*)d_in[10];
    const float* Wkg  = (const float*)d_in[11]; const float* bkg = (const float*)d_in[12];
    const float* Wvg  = (const float*)d_in[13]; const float* bvg = (const float*)d_in[14];
    const float* ln0g = (const float*)d_in[15]; const float* ln0b = (const float*)d_in[16];
    const float* ln1g = (const float*)d_in[17]; const float* ln1b = (const float*)d_in[18];
    const float* W1   = (const float*)d_in[19];
    const float* W3   = (const float*)d_in[20];
    const float* W2   = (const float*)d_in[21];
    float* out = (float*)d_out;

    float *qp, *kp, *vp, *gqp, *gkp, *gvp, *attnp, *h0p, *t1p, *t2p, *tbp;
    cudaGetSymbolAddress((void**)&qp,  g_q);
    cudaGetSymbolAddress((void**)&kp,  g_k);
    cudaGetSymbolAddress((void**)&vp,  g_v);
    cudaGetSymbolAddress((void**)&gqp, g_gq);
    cudaGetSymbolAddress((void**)&gkp, g_gk);
    cudaGetSymbolAddress((void**)&gvp, g_gv);
    cudaGetSymbolAddress((void**)&attnp, g_attn);
    cudaGetSymbolAddress((void**)&h0p, g_h0);
    cudaGetSymbolAddress((void**)&t1p, g_t1);
    cudaGetSymbolAddress((void**)&t2p, g_t2);
    cudaGetSymbolAddress((void**)&tbp, g_tbuf);

    mask_cumsum_kernel<<<BB, 256>>>(am, gm, tbp);

    // 6 projection GEMMs in one launch
    GemmArgs pa = {};
    pa.A = x; pa.N = EE; pa.K = EE; pa.epi = 1;
    pa.Wm[0] = Wq;  pa.bias[0] = bq;  pa.out[0] = qp;  pa.scale[0] = 0.125f;
    pa.Wm[1] = Wk;  pa.bias[1] = bk;  pa.out[1] = kp;  pa.scale[1] = 1.f;
    pa.Wm[2] = Wv;  pa.bias[2] = bv;  pa.out[2] = vp;  pa.scale[2] = 1.f;
    pa.Wm[3] = Wqg; pa.bias[3] = bqg; pa.out[3] = gqp; pa.scale[3] = 0.125f;
    pa.Wm[4] = Wkg; pa.bias[4] = bkg; pa.out[4] = gkp; pa.scale[4] = 1.f;
    pa.Wm[5] = Wvg; pa.bias[5] = bvg; pa.out[5] = gvp; pa.scale[5] = 1.f;
    sgemm_kernel<<<dim3(32, 6, 6), 256>>>(pa);

    rope_kernel<<<(BB*HH*SS*32 + 255)/256, 256>>>(qp, kp, tbp);

    band_attn_kernel<<<dim3(SS/16, HH, BB), 256>>>(qp, kp, vp, am, gm, attnp);
    global_attn_kernel<<<dim3(GG, HH, BB), 256>>>(gqp, gkp, gvp, am, gm, attnp);

    add_ln_kernel<<<BB*SS, 256>>>(x, attnp, ln0g, ln0b, h0p);

    GemmArgs f1 = {};
    f1.A = h0p; f1.N = FFD; f1.K = EE; f1.epi = 0;
    f1.Wm[0] = W1; f1.bias[0] = nullptr; f1.out[0] = t1p; f1.scale[0] = 1.f;
    f1.Wm[1] = W3; f1.bias[1] = nullptr; f1.out[1] = t2p; f1.scale[1] = 1.f;
    sgemm_kernel<<<dim3(32, 24, 2), 256>>>(f1);

    silu_mul_kernel<<<(NFF + 255)/256, 256>>>(t1p, t2p, NFF);

    GemmArgs f2 = {};
    f2.A = t1p; f2.N = EE; f2.K = FFD; f2.epi = 0;
    f2.Wm[0] = W2; f2.bias[0] = nullptr; f2.out[0] = attnp; f2.scale[0] = 1.f;
    sgemm_kernel<<<dim3(32, 6, 1), 256>>>(f2);

    add_ln_kernel<<<BB*SS, 256>>>(h0p, attnp, ln1g, ln1b, out);
}